// round 17
// baseline (speedup 1.0000x reference)
#include <cuda_runtime.h>
#include <math.h>
#include <stdint.h>

#define BATCH 32768
#define HALFB 16384
#define STEPS 1000
#define HID   512
#define NT    8            // coarse t-grid points over [0,1]
#define GY    64           // y-grid points
#define EPTS  (NT * GY)    // 512 coarse points
#define DT_F  0.001f
#define YLO  (-9.5f)
#define YHI  (11.5f)
#define CHUNK 20           // steps per staged chunk (1000 = 50*20)
#define NCHUNK (STEPS / CHUNK)
#define OC    2            // chunks per output writeback group (40 steps)
#define DEPTH 2            // input ring depth
#define SIM_BLOCKS 128     // <=148 SMs: uniform 1 block/SM, no imbalance
#define SIM_THREADS 128    // 4 warps -> all 4 SMSPs busy
#define KSPLIT 8           // k-slices (64 wide each)
#define BROWS 8            // grid points per build block
#define KW    64           // k-slice width
#define JT    32           // j-rows per W2 tile
#define NTILE (HID / JT)   // 16 tiles
#define MAGIC 12582912.0f  // 1.5 * 2^23

// scratch (static device arrays; no runtime allocation)
__device__ float  g_Fp[KSPLIT * EPTS];   // k-split partial sums
__device__ float4 g_C[STEPS * GY];       // per-step per-cell cubic coeffs
__device__ float  g_part[SIM_BLOCKS];    // logqp block partials
__device__ int    g_cnt = 0;             // last-block arrival counter

__device__ __forceinline__ void cp_async16(uint32_t saddr, const void* gaddr) {
    asm volatile("cp.async.cg.shared.global [%0], [%1], 16;\n" :: "r"(saddr), "l"(gaddr));
}
__device__ __forceinline__ void cp_commit() {
    asm volatile("cp.async.commit_group;\n");
}
template <int N>
__device__ __forceinline__ void cp_wait() {
    asm volatile("cp.async.wait_group %0;\n" :: "n"(N));
}

// ---------------------------------------------------------------------------
// Kernel 1 (R16-proven, 25.4us): build coarse-table partials.
// Block = 8 grid points x 64-wide k-slice -> 512 blocks; 2 j-teams of 64.
// ---------------------------------------------------------------------------
__global__ void __launch_bounds__(128)
build_partial(const float* __restrict__ W1, const float* __restrict__ b1,
              const float* __restrict__ W2, const float* __restrict__ b2,
              const float* __restrict__ W3)
{
    __shared__ __align__(16) float h1t[HID][BROWS];      // 16 KB, transposed
    __shared__ __align__(16) float wt[2][JT][KW];        // 16 KB
    __shared__ float zsum[KW][BROWS];                    // 2 KB
    __shared__ float part[2][BROWS];
    const int tid  = threadIdx.x;
    const int lane = tid & 31;
    const int team = tid >> 6;
    const int kl   = tid & 63;
    const int pg   = blockIdx.x >> 3;
    const int kb   = blockIdx.x & 7;
    const int m0   = pg * BROWS;

    for (int idx = tid; idx < BROWS * HID; idx += 128) {
        int r = idx & (BROWS - 1);
        int j = idx >> 3;
        int m = m0 + r;
        float t  = (float)(m >> 6) * (1.0f / (float)(NT - 1));
        float yv = YLO + (float)(m & (GY - 1)) * ((YHI - YLO) / (float)(GY - 1));
        h1t[j][r] = tanhf(t * W1[j] + yv * W1[HID + j] + b1[j]);
    }

    const int k = kb * KW + kl;
    const float* __restrict__ wsrc = W2 + kb * KW;
    uint32_t wtA[2];
    wtA[0] = (uint32_t)__cvta_generic_to_shared(&wt[0][0][0]);
    wtA[1] = (uint32_t)__cvta_generic_to_shared(&wt[1][0][0]);

    auto issue = [&](int t, int buf) {
        const float* src0 = wsrc + t * JT * HID;
        #pragma unroll
        for (int q = 0; q < 4; ++q) {
            int idx = tid + 128 * q;        // 0..511
            int jj  = idx >> 4;
            int kk  = idx & 15;
            cp_async16(wtA[buf] + (uint32_t)((jj * KW + kk * 4) * 4),
                       src0 + jj * HID + kk * 4);
        }
        cp_commit();
    };

    issue(0, 0);
    issue(1, 1);
    __syncthreads();

    float a[BROWS];
    #pragma unroll
    for (int r = 0; r < BROWS; ++r) a[r] = 0.f;

    #pragma unroll 1
    for (int t = 0; t < NTILE; ++t) {
        if (t + 1 < NTILE) cp_wait<1>(); else cp_wait<0>();
        __syncthreads();

        const int j0 = t * JT + team * 16;
        const float* wcol = &wt[t & 1][team * 16][kl];
        const float4* hrow = (const float4*)&h1t[j0][0];
        #pragma unroll
        for (int jj = 0; jj < 16; ++jj) {
            float4 hA = hrow[2 * jj];
            float4 hB = hrow[2 * jj + 1];
            float  w  = wcol[jj * KW];
            a[0] = fmaf(hA.x, w, a[0]);
            a[1] = fmaf(hA.y, w, a[1]);
            a[2] = fmaf(hA.z, w, a[2]);
            a[3] = fmaf(hA.w, w, a[3]);
            a[4] = fmaf(hB.x, w, a[4]);
            a[5] = fmaf(hB.y, w, a[5]);
            a[6] = fmaf(hB.z, w, a[6]);
            a[7] = fmaf(hB.w, w, a[7]);
        }
        __syncthreads();
        if (t + 2 < NTILE) issue(t + 2, t & 1);
    }

    if (team == 1) {
        #pragma unroll
        for (int r = 0; r < BROWS; ++r) zsum[kl][r] = a[r];
    }
    __syncthreads();

    if (team == 0) {
        float bk = b2[k];
        float wk = W3[k];
        float fs[BROWS];
        #pragma unroll
        for (int r = 0; r < BROWS; ++r)
            fs[r] = tanhf(a[r] + zsum[kl][r] + bk) * wk;

        #pragma unroll
        for (int off = 16; off > 0; off >>= 1) {
            #pragma unroll
            for (int r = 0; r < BROWS; ++r)
                fs[r] += __shfl_xor_sync(0xFFFFFFFFu, fs[r], off);
        }
        if (lane == 0) {
            int w01 = tid >> 5;
            #pragma unroll
            for (int r = 0; r < BROWS; ++r) part[w01][r] = fs[r];
        }
    }
    __syncthreads();
    if (tid < BROWS) {
        g_Fp[kb * EPTS + m0 + tid] = part[0][tid] + part[1][tid];
    }
}

// ---------------------------------------------------------------------------
// Kernel 2 (fused): combine 8 k-split partials -> coarse table (smem) ->
// t-interp (4-pt Lagrange) + y-stencil -> power-basis cubic coeffs.
// ---------------------------------------------------------------------------
__global__ void __launch_bounds__(256)
expand_coef_fused(const float* __restrict__ b3)
{
    __shared__ float Fc[NT][GY];
    const int tid = threadIdx.x;
    float bb = b3[0];
    for (int i = tid; i < EPTS; i += 256) {
        float s = bb;
        #pragma unroll
        for (int p = 0; p < KSPLIT; ++p) s += g_Fp[p * EPTS + i];
        Fc[i >> 6][i & 63] = s;
    }
    __syncthreads();

    int idx = blockIdx.x * 256 + tid;
    if (idx >= STEPS * GY) return;
    int s = idx >> 6;
    int g = idx & (GY - 1);

    float t = (float)s * DT_F;
    float xf = t * (float)(NT - 1);
    int i = (int)xf;
    i = min(max(i, 1), NT - 3);
    float a = xf - (float)i;
    float wm1 = -a * (a - 1.f) * (a - 2.f) * (1.f / 6.f);
    float w0  = (a + 1.f) * (a - 1.f) * (a - 2.f) * 0.5f;
    float w1  = -(a + 1.f) * a * (a - 2.f) * 0.5f;
    float w2  = (a + 1.f) * a * (a - 1.f) * (1.f / 6.f);

    float v[4];
    #pragma unroll
    for (int j = 0; j < 4; ++j) {
        int gc = min(max(g - 1 + j, 0), GY - 1);
        v[j] = wm1 * Fc[i - 1][gc] + w0 * Fc[i][gc]
             + w1  * Fc[i + 1][gc] + w2 * Fc[i + 2][gc];
    }
    float4 c;
    c.x = v[1];
    c.y = -v[0] * (1.f / 3.f) - 0.5f * v[1] + v[2] - v[3] * (1.f / 6.f);
    c.z = 0.5f * v[0] - v[1] + 0.5f * v[2];
    c.w = (v[3] - v[0]) * (1.f / 6.f) + 0.5f * (v[1] - v[2]);
    g_C[idx] = c;
}

// ---------------------------------------------------------------------------
// Kernel 3: simulation + fused finalize. 128 blocks x 128 threads, TWO
// samples per thread (b, b+16384): uniform 1 block/SM (122 KB smem), no
// dual-block crossbar contention, chain latency hidden by 2 interleaved
// chains. Table + dW smem double-buffered via cp.async (distance-1 = 20
// steps). Outputs staged 40 steps in padded smem, 128B-contiguous writeback.
// ---------------------------------------------------------------------------
__global__ void __launch_bounds__(SIM_THREADS)
sim_kernel(const float* __restrict__ eps, const float* __restrict__ dW,
           const float* __restrict__ qm, const float* __restrict__ qlv,
           float* __restrict__ out)
{
    __shared__ __align__(16) float4 tabs[DEPTH][CHUNK * GY];             // 40 KB
    __shared__ __align__(16) float  dws[DEPTH][CHUNK][2][SIM_THREADS];   // 40 KB
    __shared__ __align__(16) float  ost[2][SIM_THREADS][OC * CHUNK + 1]; // 42 KB
    __shared__ float red[SIM_THREADS];
    __shared__ int isLast;

    const int tid  = threadIdx.x;
    const int warp = tid >> 5;
    const int lane = tid & 31;
    const int blkbase = blockIdx.x * SIM_THREADS;
    const int b0 = blkbase + tid;

    float qstd = expf(0.5f * qlv[0]);
    float qmv  = qm[0];
    float y0 = qmv + eps[b0] * qstd;
    float y1 = qmv + eps[b0 + HALFB] * qstd;
    float lq = 0.f;
    const float invH = (float)(GY - 1) / (YHI - YLO);
    const float offc = -YLO * invH;
    const float DTH  = DT_F * invH;
    float xf0 = fmaf(y0, invH, offc);
    float xf1 = fmaf(y1, invH, offc);

    uint32_t tabA[DEPTH], dwA[DEPTH];
    #pragma unroll
    for (int d = 0; d < DEPTH; ++d) {
        tabA[d] = (uint32_t)__cvta_generic_to_shared(&tabs[d][0]);
        dwA[d]  = (uint32_t)__cvta_generic_to_shared(&dws[d][0][0][0]);
    }

    // chunk issuer: table 1280 f4 (10/thr) + dW 1280 f4 (10/thr, 2 groups)
    auto issue = [&](int c) {
        int buf = c & 1;
        const float4* tsrc = g_C + c * (CHUNK * GY);
        #pragma unroll
        for (int q = 0; q < CHUNK * GY / SIM_THREADS; ++q)
            cp_async16(tabA[buf] + (tid + SIM_THREADS * q) * 16,
                       tsrc + tid + SIM_THREADS * q);
        const float4* dsrc = (const float4*)(dW + (size_t)c * CHUNK * BATCH);
        const int dstride4 = BATCH / 4;
        const int base4 = blkbase / 4;
        #pragma unroll
        for (int q = 0; q < 10; ++q) {
            int idx = tid + SIM_THREADS * q;     // 0..1279
            int s   = idx >> 6;                  // step in chunk
            int grp = (idx >> 5) & 1;            // sample group
            int l   = idx & 31;                  // float4 within 128-row
            cp_async16(dwA[buf] + (uint32_t)(idx * 16),
                       dsrc + (size_t)s * dstride4 + base4
                            + grp * (HALFB / 4) + l);
        }
        cp_commit();
    };

    issue(0);

    for (int c = 0; c < NCHUNK; ++c) {
        const int cur = c & 1;
        cp_wait<0>();      // group c complete (issued one full chunk ago)
        __syncthreads();   // visible to all; buffer (c+1)&1 fully consumed

        if (c + 1 < NCHUNK) issue(c + 1);

        const float4* tb = &tabs[cur][0];
        const int pos0 = (c & (OC - 1)) * CHUNK;
        #pragma unroll
        for (int ii = 0; ii < CHUNK; ++ii) {
            // off-chain precomputation (depends only on previous y)
            float dv0 = dws[cur][ii][0][tid];
            float dv1 = dws[cur][ii][1][tid];
            float z0  = fmaf(dv0, 0.5f, y0);
            float z1  = fmaf(dv1, 0.5f, y1);
            float wv0 = fmaf(z0, invH, offc);
            float wv1 = fmaf(z1, invH, offc);
            float ym0 = y0 - 1.0f;
            float ym1 = y1 - 1.0f;

            // two independent critical chains, interleaved
            float mg0 = xf0 + MAGIC;
            float mg1 = xf1 + MAGIC;
            int bt0 = __float_as_int(mg0);
            int bt1 = __float_as_int(mg1);
            float a0 = xf0 - (mg0 - MAGIC);
            float a1 = xf1 - (mg1 - MAGIC);
            const char* rb = (const char*)(tb + ii * GY);
            float4 c0 = *(const float4*)(rb + ((bt0 & (GY - 1)) << 4));
            float4 c1 = *(const float4*)(rb + ((bt1 & (GY - 1)) << 4));
            float a20 = a0 * a0;
            float a21 = a1 * a1;
            float f0 = fmaf(a20, fmaf(c0.w, a0, c0.z), fmaf(c0.y, a0, c0.x));
            float f1 = fmaf(a21, fmaf(c1.w, a1, c1.z), fmaf(c1.y, a1, c1.x));

            float s0 = f0 + ym0;
            float s1 = f1 + ym1;
            lq = fmaf(s0 * s0 + s1 * s1, 2.0f * DT_F, lq);

            xf0 = fmaf(f0, DTH, wv0);
            xf1 = fmaf(f1, DTH, wv1);
            y0  = fmaf(f0, DT_F, z0);
            y1  = fmaf(f1, DT_F, z1);
            ost[0][tid][pos0 + ii] = y0;       // stride 41: conflict-free
            ost[1][tid][pos0 + ii] = y1;
        }

        // writeback every OC chunks; rows warp-local
        if ((c & (OC - 1)) == OC - 1) {
            __syncwarp();
            const int sbase = (c >> 1) * (OC * CHUNK);
            #pragma unroll
            for (int g = 0; g < 2; ++g) {
                #pragma unroll 4
                for (int rr = 0; rr < 32; ++rr) {
                    int r = warp * 32 + rr;
                    out[(size_t)(blkbase + g * HALFB + r) * STEPS + sbase + lane]
                        = ost[g][r][lane];
                }
            }
            // tails: steps 32..39, 64 rows (2 groups) x 8 steps per warp
            #pragma unroll
            for (int kq = 0; kq < 16; ++kq) {
                int idx = kq * 32 + lane;          // 0..511
                int row64 = idx >> 3;              // 0..63
                int g = row64 >> 5;
                int r = warp * 32 + (row64 & 31);
                int s = 32 + (idx & 7);
                out[(size_t)(blkbase + g * HALFB + r) * STEPS + sbase + s]
                    = ost[g][r][s];
            }
            __syncwarp();
        }
    }

    // deterministic block reduction of logqp
    red[tid] = lq;
    __syncthreads();
    #pragma unroll
    for (int off = SIM_THREADS / 2; off > 0; off >>= 1) {
        if (tid < off) red[tid] += red[tid + off];
        __syncthreads();
    }
    if (tid == 0) {
        g_part[blockIdx.x] = red[0];
        __threadfence();
        int old = atomicAdd(&g_cnt, 1);
        isLast = (old == SIM_BLOCKS - 1) ? 1 : 0;
    }
    __syncthreads();

    if (isLast) {
        __threadfence();   // acquire all blocks' g_part stores
        red[tid] = g_part[tid];     // 128 partials, 128 threads
        __syncthreads();
        #pragma unroll
        for (int off = SIM_THREADS / 2; off > 0; off >>= 1) {
            if (tid < off) red[tid] += red[tid + off];
            __syncthreads();
        }
        if (tid == 0) {
            float pystd = 0.5f / sqrtf(2.0f);
            float r = qstd / pystd;
            float dm = 1.0f - qmv;
            float kl0 = 0.5f * (r * r + dm * dm / (pystd * pystd)
                                - 1.0f + logf(pystd / qstd));
            out[(size_t)BATCH * STEPS] = kl0 + red[0] / (float)BATCH;
            g_cnt = 0;
        }
    }
}

// ---------------------------------------------------------------------------
extern "C" void kernel_launch(void* const* d_in, const int* in_sizes, int n_in,
                              void* d_out, int out_size)
{
    const float* W1  = (const float*)d_in[0];
    const float* b1  = (const float*)d_in[1];
    const float* W2  = (const float*)d_in[2];
    const float* b2  = (const float*)d_in[3];
    const float* W3  = (const float*)d_in[4];
    const float* b3  = (const float*)d_in[5];
    const float* qm  = (const float*)d_in[6];
    const float* qlv = (const float*)d_in[7];
    const float* eps = (const float*)d_in[8];
    const float* dW  = (const float*)d_in[9];
    float* out = (float*)d_out;

    build_partial<<<(EPTS / BROWS) * KSPLIT, 128>>>(W1, b1, W2, b2, W3);
    expand_coef_fused<<<(STEPS * GY + 255) / 256, 256>>>(b3);
    sim_kernel<<<SIM_BLOCKS, SIM_THREADS>>>(eps, dW, qm, qlv, out);
}